// round 1
// baseline (speedup 1.0000x reference)
#include <cuda_runtime.h>
#include <math.h>

// Problem constants
#define T_   12
#define B_   16
#define N_   2048
#define D_   128
#define F_   1536   // T_*D_  (per-node feature length)
#define KTOP 5
#define NEG_SLOPE 0.01f

// Scratch (device globals — allocation-free per harness rules)
__device__ float g_xn[(size_t)B_ * N_ * F_];    // normalized features [B, N, F] (~402 MB)
__device__ float g_dist[(size_t)B_ * N_ * N_];  // Gram matrix [B, N, N]          (~268 MB)

// ---------------------------------------------------------------------------
// K1: gather x[t,b,n,d] -> xf[b,n,t*D+d], row-normalize (cosine prep)
// One block per (n, b); 256 threads x 6 elements = 1536.
// ---------------------------------------------------------------------------
__global__ __launch_bounds__(256) void pack_norm_kernel(const float* __restrict__ x) {
    int n = blockIdx.x, b = blockIdx.y, tid = threadIdx.x;
    float vals[6];
    float ss = 0.f;
#pragma unroll
    for (int j = 0; j < 6; j++) {
        int idx = tid + j * 256;
        int t = idx >> 7, d = idx & 127;
        float v = x[(((size_t)t * B_ + b) * N_ + n) * D_ + d];
        vals[j] = v;
        ss += v * v;
    }
    __shared__ float red[256];
    red[tid] = ss;
    __syncthreads();
    for (int s = 128; s > 0; s >>= 1) {
        if (tid < s) red[tid] += red[tid + s];
        __syncthreads();
    }
    float r = rsqrtf(red[0]);
    float* o = g_xn + ((size_t)b * N_ + n) * F_;
#pragma unroll
    for (int j = 0; j < 6; j++) o[tid + j * 256] = vals[j] * r;
}

// ---------------------------------------------------------------------------
// K2: batched symmetric Gram matrix  dist[b] = XN[b] @ XN[b]^T
// Upper-triangular 128x128 tile pairs only (136 per batch), mirror on write.
// Classic SIMT fp32 GEMM: BM=BN=128, BK=16, 256 threads, 8x8 per thread.
// ---------------------------------------------------------------------------
__global__ __launch_bounds__(256) void gemm_sym_kernel() {
    const int NBLK = N_ / 128;  // 16 row-blocks
    int p = blockIdx.x, b = blockIdx.y;

    // map linear pair index -> (bi, bj), bi <= bj
    int bi = 0, rem = p;
    while (rem >= NBLK - bi) { rem -= NBLK - bi; bi++; }
    int bj = bi + rem;

    const float* Abase = g_xn + (size_t)b * N_ * F_ + (size_t)bi * 128 * F_;
    const float* Bbase = g_xn + (size_t)b * N_ * F_ + (size_t)bj * 128 * F_;

    __shared__ float As[16][132];  // [k][row], padded (132*4 = 528 B, 16B aligned rows)
    __shared__ float Bs[16][132];

    int tid = threadIdx.x;
    int tx = tid & 15, ty = tid >> 4;

    float acc[8][8];
#pragma unroll
    for (int m = 0; m < 8; m++)
#pragma unroll
        for (int n2 = 0; n2 < 8; n2++) acc[m][n2] = 0.f;

    for (int k0 = 0; k0 < F_; k0 += 16) {
        // cooperative load: 128 rows x 16 k-cols per tile, float4 per thread x2
#pragma unroll
        for (int s = 0; s < 2; s++) {
            int f   = tid + s * 256;       // float4 index 0..511
            int row = f >> 2;
            int c   = (f & 3) << 2;
            float4 va = *(const float4*)(Abase + (size_t)row * F_ + k0 + c);
            float4 vb = *(const float4*)(Bbase + (size_t)row * F_ + k0 + c);
            As[c + 0][row] = va.x; As[c + 1][row] = va.y;
            As[c + 2][row] = va.z; As[c + 3][row] = va.w;
            Bs[c + 0][row] = vb.x; Bs[c + 1][row] = vb.y;
            Bs[c + 2][row] = vb.z; Bs[c + 3][row] = vb.w;
        }
        __syncthreads();

#pragma unroll
        for (int kk = 0; kk < 16; kk++) {
            float4 a0 = *(const float4*)&As[kk][ty * 8];
            float4 a1 = *(const float4*)&As[kk][ty * 8 + 4];
            float4 b0 = *(const float4*)&Bs[kk][tx * 8];
            float4 b1 = *(const float4*)&Bs[kk][tx * 8 + 4];
            float a[8]  = {a0.x, a0.y, a0.z, a0.w, a1.x, a1.y, a1.z, a1.w};
            float bb[8] = {b0.x, b0.y, b0.z, b0.w, b1.x, b1.y, b1.z, b1.w};
#pragma unroll
            for (int m = 0; m < 8; m++)
#pragma unroll
                for (int n2 = 0; n2 < 8; n2++)
                    acc[m][n2] = fmaf(a[m], bb[n2], acc[m][n2]);
        }
        __syncthreads();
    }

    float* Db = g_dist + (size_t)b * N_ * N_;
    int gi = bi * 128 + ty * 8;
    int gj = bj * 128 + tx * 8;
#pragma unroll
    for (int m = 0; m < 8; m++) {
        *(float4*)&Db[(size_t)(gi + m) * N_ + gj] =
            make_float4(acc[m][0], acc[m][1], acc[m][2], acc[m][3]);
        *(float4*)&Db[(size_t)(gi + m) * N_ + gj + 4] =
            make_float4(acc[m][4], acc[m][5], acc[m][6], acc[m][7]);
    }
    if (bi != bj) {
        // mirror into the lower-triangular tile (transposed)
#pragma unroll
        for (int n2 = 0; n2 < 8; n2++)
#pragma unroll
            for (int m = 0; m < 8; m++)
                Db[(size_t)(gj + n2) * N_ + gi + m] = acc[m][n2];
    }
}

// ---------------------------------------------------------------------------
// K3: per-row top-5 (jax tie-break = lowest index) + fused symmetric scatter:
//   out[b,i,j] += 0.5*lrelu(v);  out[b,j,i] += 0.5*lrelu(v)
// out must be zeroed beforehand (memset in kernel_launch).
// ---------------------------------------------------------------------------
__global__ __launch_bounds__(256) void topk_scatter_kernel(float* __restrict__ out) {
    int i = blockIdx.x, b = blockIdx.y, tid = threadIdx.x;
    const float* drow = g_dist + ((size_t)b * N_ + i) * N_;

    __shared__ float sv[N_];
    __shared__ float rv[256];
    __shared__ int   ri[256];
    __shared__ float selV[KTOP];
    __shared__ int   selI[KTOP];

#pragma unroll
    for (int j = 0; j < N_ / 256; j++) sv[tid + j * 256] = drow[tid + j * 256];
    __syncthreads();

    for (int k = 0; k < KTOP; k++) {
        float bv = -INFINITY;
        int bidx = 0x7fffffff;
#pragma unroll
        for (int j = 0; j < N_ / 256; j++) {
            int idx = tid + j * 256;
            float v = sv[idx];
            if (v > bv) { bv = v; bidx = idx; }  // ascending idx: strict > keeps lowest idx
        }
        rv[tid] = bv;
        ri[tid] = bidx;
        __syncthreads();
        for (int s = 128; s > 0; s >>= 1) {
            if (tid < s) {
                float v2 = rv[tid + s];
                int   i2 = ri[tid + s];
                if (v2 > rv[tid] || (v2 == rv[tid] && i2 < ri[tid])) {
                    rv[tid] = v2;
                    ri[tid] = i2;
                }
            }
            __syncthreads();
        }
        if (tid == 0) {
            selV[k] = rv[0];
            selI[k] = ri[0];
            sv[ri[0]] = -INFINITY;  // exclude from next pass
        }
        __syncthreads();
    }

    if (tid < KTOP) {
        float v = selV[tid];
        int   j = selI[tid];
        float w = 0.5f * (v >= 0.f ? v : NEG_SLOPE * v);  // 0.5 * leaky_relu * weight(1.0)
        float* ob = out + (size_t)b * N_ * N_;
        atomicAdd(&ob[(size_t)i * N_ + j], w);
        atomicAdd(&ob[(size_t)j * N_ + i], w);
    }
}

// ---------------------------------------------------------------------------
extern "C" void kernel_launch(void* const* d_in, const int* in_sizes, int n_in,
                              void* d_out, int out_size) {
    const float* x = (const float*)d_in[0];
    float* out = (float*)d_out;

    pack_norm_kernel<<<dim3(N_, B_), 256>>>(x);
    gemm_sym_kernel<<<dim3(136, B_), 256>>>();
    cudaMemsetAsync(d_out, 0, (size_t)out_size * sizeof(float), 0);
    topk_scatter_kernel<<<dim3(N_, B_), 256>>>(out);
}